// round 1
// baseline (speedup 1.0000x reference)
#include <cuda_runtime.h>
#include <math.h>

// Problem constants
constexpr int BATCH = 2;
constexpr int SEQ   = 160;
constexpr int DIM   = 768;
constexpr int HD    = 128;
constexpr int HD1   = 129;
constexpr int RANK  = 4;
constexpr int BL    = BATCH * SEQ;          // 320
constexpr int NB    = BATCH * RANK * SEQ;   // 1280 (b,r,y) batches
constexpr int KJ    = HD * HD1;             // 16512

// Scratch (device globals: allocation-free)
static __device__ float g_hidden [BL * 4 * HD];        // [bl, 512]
static __device__ float g_scoring[BL * 2 * HD];        // [bl, 256]
static __device__ float g_hinT   [BATCH * HD1 * SEQ];  // [b, j, z] (j=128 row = ones)
static __device__ float g_WfT    [HD1 * KJ];           // [m, n*128+q]
static __device__ float g_A      [BL * RANK * KJ];     // [(b,y), r, k*129+j]
static __device__ float g_t      [BL * KJ];            // [(b,y), n*128+q]
static __device__ float g_v      [BL * SEQ * HD];      // [(b,y), x, q]
static __device__ float g_Dm     [(size_t)NB * SEQ * HD1]; // [beta, x, j]
static __device__ float g_logits [(size_t)NB * SEQ * SEQ]; // [beta, x, z]
static __device__ float g_span   [(size_t)NB * SEQ * HD];  // [beta, x, h]
static __device__ float g_span2  [(size_t)NB * SEQ * HD];

// ---------------------------------------------------------------------------
// Generic guarded 64x64x16 tile GEMM core. 256 threads, 4x4 microtile.
// A element (row,k) at Ab[row*as_m + k*as_k]; B element (k,col) at
// Bb[k*bs_k + col*bs_n].
// ---------------------------------------------------------------------------
__device__ __forceinline__ void gemm_core(
    const float* __restrict__ Ab, long as_m, long as_k,
    const float* __restrict__ Bb, long bs_k, long bs_n,
    int M, int N, int K, int row0, int col0,
    float (&acc)[4][4], float* As /*16*65*/, float* Bs /*16*64*/)
{
    const int tid = threadIdx.x;
    const int tx  = tid & 15;
    const int ty  = tid >> 4;
    for (int k0 = 0; k0 < K; k0 += 16) {
        {
            int idx = tid;
            #pragma unroll
            for (int l = 0; l < 4; l++, idx += 256) {
                int kk = idx & 15;
                int m  = idx >> 4;
                int gr = row0 + m, gk = k0 + kk;
                float v = 0.f;
                if (gr < M && gk < K) v = Ab[(long)gr * as_m + (long)gk * as_k];
                As[kk * 65 + m] = v;
            }
            idx = tid;
            #pragma unroll
            for (int l = 0; l < 4; l++, idx += 256) {
                int n  = idx & 63;
                int kk = idx >> 6;
                int gc = col0 + n, gk = k0 + kk;
                float v = 0.f;
                if (gc < N && gk < K) v = Bb[(long)gk * bs_k + (long)gc * bs_n];
                Bs[kk * 64 + n] = v;
            }
        }
        __syncthreads();
        #pragma unroll
        for (int kk = 0; kk < 16; kk++) {
            float a[4], b[4];
            #pragma unroll
            for (int i = 0; i < 4; i++) a[i] = As[kk * 65 + ty * 4 + i];
            #pragma unroll
            for (int j = 0; j < 4; j++) b[j] = Bs[kk * 64 + tx * 4 + j];
            #pragma unroll
            for (int i = 0; i < 4; i++)
                #pragma unroll
                for (int j = 0; j < 4; j++)
                    acc[i][j] = fmaf(a[i], b[j], acc[i][j]);
        }
        __syncthreads();
    }
}

__device__ __forceinline__ float leaky(float v) { return v >= 0.f ? v : 0.1f * v; }

// ---------------------------------------------------------------------------
// K1: hidden/scoring MLP: C[BL,N] = leaky(X[BL,768] @ W[768,N] + bias)
// ---------------------------------------------------------------------------
__global__ __launch_bounds__(256) void k_mlp(
    const float* __restrict__ X, const float* __restrict__ W,
    const float* __restrict__ bias, float* __restrict__ C, int N)
{
    __shared__ float As[16 * 65], Bs[16 * 64];
    int row0 = blockIdx.y * 64, col0 = blockIdx.x * 64;
    float acc[4][4] = {};
    gemm_core(X, DIM, 1, W, N, 1, BL, N, DIM, row0, col0, acc, As, Bs);
    int ty = threadIdx.x >> 4, tx = threadIdx.x & 15;
    #pragma unroll
    for (int i = 0; i < 4; i++) {
        int r = row0 + ty * 4 + i;
        if (r >= BL) continue;
        #pragma unroll
        for (int j = 0; j < 4; j++) {
            int c = col0 + tx * 4 + j;
            if (c < N) C[(long)r * N + c] = leaky(acc[i][j] + bias[c]);
        }
    }
}

// transpose h_in into [b, j, z], j=128 row = ones
__global__ void k_hinT() {
    int idx = blockIdx.x * 256 + threadIdx.x;
    if (idx >= BATCH * HD1 * SEQ) return;
    int z = idx % SEQ;
    int j = (idx / SEQ) % HD1;
    int b = idx / (SEQ * HD1);
    g_hinT[idx] = (j < HD) ? g_hidden[(b * SEQ + z) * 512 + 384 + j] : 1.0f;
}

// transpose W_final[n,q,m] -> WfT[m, n*128+q]
__global__ void k_wfT(const float* __restrict__ Wf) {
    int idx = blockIdx.x * 256 + threadIdx.x;
    if (idx >= HD1 * KJ) return;
    int nq = idx % KJ;
    int m  = idx / KJ;
    g_WfT[idx] = Wf[(long)nq * HD1 + m];
}

// ---------------------------------------------------------------------------
// K2: A[(b,y), r, k*129+j] = sum_i h_tail[by,i]*Wtri[r,i,k,j] + Wtri[r,128,k,j]
// ---------------------------------------------------------------------------
__global__ __launch_bounds__(256) void k_A(const float* __restrict__ Wtri)
{
    __shared__ float As[16 * 65], Bs[16 * 64];
    int r = blockIdx.z;
    int row0 = blockIdx.y * 64, col0 = blockIdx.x * 64;
    const float* Wr = Wtri + (size_t)r * HD1 * KJ;
    float acc[4][4] = {};
    gemm_core(g_hidden + 256, 512, 1, Wr, KJ, 1, BL, KJ, HD, row0, col0, acc, As, Bs);
    const float* brow = Wr + (size_t)HD * KJ;
    int ty = threadIdx.x >> 4, tx = threadIdx.x & 15;
    #pragma unroll
    for (int i = 0; i < 4; i++) {
        int m = row0 + ty * 4 + i;
        if (m >= BL) continue;
        #pragma unroll
        for (int j = 0; j < 4; j++) {
            int c = col0 + tx * 4 + j;
            if (c < KJ) g_A[((size_t)m * RANK + r) * KJ + c] = acc[i][j] + brow[c];
        }
    }
}

// ---------------------------------------------------------------------------
// K3: t[(b,y), n*128+q] = sum_m x_tail[by,m]*WfT[m,nq] + WfT[128,nq]
// ---------------------------------------------------------------------------
__global__ __launch_bounds__(256) void k_t()
{
    __shared__ float As[16 * 65], Bs[16 * 64];
    int row0 = blockIdx.y * 64, col0 = blockIdx.x * 64;
    float acc[4][4] = {};
    gemm_core(g_scoring + 128, 256, 1, g_WfT, KJ, 1, BL, KJ, HD, row0, col0, acc, As, Bs);
    int ty = threadIdx.x >> 4, tx = threadIdx.x & 15;
    #pragma unroll
    for (int i = 0; i < 4; i++) {
        int m = row0 + ty * 4 + i;
        if (m >= BL) continue;
        #pragma unroll
        for (int j = 0; j < 4; j++) {
            int c = col0 + tx * 4 + j;
            if (c < KJ) g_t[(size_t)m * KJ + c] = acc[i][j] + g_WfT[(size_t)HD * KJ + c];
        }
    }
}

// ---------------------------------------------------------------------------
// K4: v[(b,y), x, q] = sum_n x_head[b,x,n]*t[by,n,q] + t[by,128,q]
// grid (2, 3, 320)
// ---------------------------------------------------------------------------
__global__ __launch_bounds__(256) void k_v()
{
    __shared__ float As[16 * 65], Bs[16 * 64];
    int beta = blockIdx.z;          // (b,y)
    int b = beta / SEQ;
    int row0 = blockIdx.y * 64, col0 = blockIdx.x * 64;
    const float* tb = g_t + (size_t)beta * KJ;
    float acc[4][4] = {};
    gemm_core(g_scoring + (long)b * SEQ * 256, 256, 1, tb, HD, 1,
              SEQ, HD, HD, row0, col0, acc, As, Bs);
    int ty = threadIdx.x >> 4, tx = threadIdx.x & 15;
    #pragma unroll
    for (int i = 0; i < 4; i++) {
        int m = row0 + ty * 4 + i;
        if (m >= SEQ) continue;
        #pragma unroll
        for (int j = 0; j < 4; j++) {
            int c = col0 + tx * 4 + j;
            if (c < HD) g_v[((size_t)beta * SEQ + m) * HD + c] = acc[i][j] + tb[HD * HD + c];
        }
    }
}

// ---------------------------------------------------------------------------
// K5: D[beta, x, j] = sum_k h_head[b,x,k] * A[(b,y),r,k,j]   beta=(b*R+r)*L+y
// grid (3, 3, 1280)
// ---------------------------------------------------------------------------
__global__ __launch_bounds__(256) void k_D()
{
    __shared__ float As[16 * 65], Bs[16 * 64];
    int beta = blockIdx.z;
    int b = beta / (RANK * SEQ);
    int r = (beta / SEQ) % RANK;
    int y = beta % SEQ;
    int row0 = blockIdx.y * 64, col0 = blockIdx.x * 64;
    float acc[4][4] = {};
    gemm_core(g_hidden + (long)b * SEQ * 512 + 128, 512, 1,
              g_A + ((size_t)(b * SEQ + y) * RANK + r) * KJ, HD1, 1,
              SEQ, HD1, HD, row0, col0, acc, As, Bs);
    float* out = g_Dm + (size_t)beta * SEQ * HD1;
    int ty = threadIdx.x >> 4, tx = threadIdx.x & 15;
    #pragma unroll
    for (int i = 0; i < 4; i++) {
        int m = row0 + ty * 4 + i;
        if (m >= SEQ) continue;
        #pragma unroll
        for (int j = 0; j < 4; j++) {
            int c = col0 + tx * 4 + j;
            if (c < HD1) out[(long)m * HD1 + c] = acc[i][j];
        }
    }
}

// ---------------------------------------------------------------------------
// K6: logits[beta, x, z] = sum_{j<129} D[beta,x,j] * hinT[b,j,z]
// grid (3, 3, 1280)
// ---------------------------------------------------------------------------
__global__ __launch_bounds__(256) void k_logits()
{
    __shared__ float As[16 * 65], Bs[16 * 64];
    int beta = blockIdx.z;
    int b = beta / (RANK * SEQ);
    int row0 = blockIdx.y * 64, col0 = blockIdx.x * 64;
    float acc[4][4] = {};
    gemm_core(g_Dm + (size_t)beta * SEQ * HD1, HD1, 1,
              g_hinT + (long)b * HD1 * SEQ, SEQ, 1,
              SEQ, SEQ, HD1, row0, col0, acc, As, Bs);
    float* out = g_logits + (size_t)beta * SEQ * SEQ;
    int ty = threadIdx.x >> 4, tx = threadIdx.x & 15;
    #pragma unroll
    for (int i = 0; i < 4; i++) {
        int m = row0 + ty * 4 + i;
        if (m >= SEQ) continue;
        #pragma unroll
        for (int j = 0; j < 4; j++) {
            int c = col0 + tx * 4 + j;
            if (c < SEQ) out[(long)m * SEQ + c] = acc[i][j];
        }
    }
}

// ---------------------------------------------------------------------------
// K7: softmax in place over z. One warp per row of 160.
// ---------------------------------------------------------------------------
__global__ __launch_bounds__(256) void k_softmax()
{
    int row = blockIdx.x * 8 + (threadIdx.x >> 5);
    int lane = threadIdx.x & 31;
    if (row >= NB * SEQ) return;
    float* p = g_logits + (size_t)row * SEQ;
    float vals[5];
    float mx = -1e30f;
    #pragma unroll
    for (int i = 0; i < 5; i++) { vals[i] = p[lane + 32 * i]; mx = fmaxf(mx, vals[i]); }
    #pragma unroll
    for (int o = 16; o; o >>= 1) mx = fmaxf(mx, __shfl_xor_sync(0xffffffffu, mx, o));
    float s = 0.f;
    #pragma unroll
    for (int i = 0; i < 5; i++) { vals[i] = expf(vals[i] - mx); s += vals[i]; }
    #pragma unroll
    for (int o = 16; o; o >>= 1) s += __shfl_xor_sync(0xffffffffu, s, o);
    float inv = 1.f / s;
    #pragma unroll
    for (int i = 0; i < 5; i++) p[lane + 32 * i] = vals[i] * inv;
}

// ---------------------------------------------------------------------------
// K8: span[beta, x, h] = sum_z alpha[beta,x,z] * h_in_repr[b,z,h]
// grid (2, 3, 1280)
// ---------------------------------------------------------------------------
__global__ __launch_bounds__(256) void k_span()
{
    __shared__ float As[16 * 65], Bs[16 * 64];
    int beta = blockIdx.z;
    int b = beta / (RANK * SEQ);
    int row0 = blockIdx.y * 64, col0 = blockIdx.x * 64;
    float acc[4][4] = {};
    gemm_core(g_logits + (size_t)beta * SEQ * SEQ, SEQ, 1,
              g_hidden + (long)b * SEQ * 512, 512, 1,
              SEQ, HD, SEQ, row0, col0, acc, As, Bs);
    float* out = g_span + (size_t)beta * SEQ * HD;
    int ty = threadIdx.x >> 4, tx = threadIdx.x & 15;
    #pragma unroll
    for (int i = 0; i < 4; i++) {
        int m = row0 + ty * 4 + i;
        if (m >= SEQ) continue;
        #pragma unroll
        for (int j = 0; j < 4; j++) {
            int c = col0 + tx * 4 + j;
            if (c < HD) out[(long)m * HD + c] = acc[i][j];
        }
    }
}

// ---------------------------------------------------------------------------
// K9: span2 = leaky(span @ W_spanmlp + b)  M = NB*SEQ = 204800
// grid (2, 3200)
// ---------------------------------------------------------------------------
__global__ __launch_bounds__(256) void k_mlp2(
    const float* __restrict__ Wsm, const float* __restrict__ bsm)
{
    __shared__ float As[16 * 65], Bs[16 * 64];
    int row0 = blockIdx.y * 64, col0 = blockIdx.x * 64;
    float acc[4][4] = {};
    gemm_core(g_span, HD, 1, Wsm, HD, 1, NB * SEQ, HD, HD, row0, col0, acc, As, Bs);
    int ty = threadIdx.x >> 4, tx = threadIdx.x & 15;
    #pragma unroll
    for (int i = 0; i < 4; i++) {
        int m = row0 + ty * 4 + i;
        if (m >= NB * SEQ) continue;
        #pragma unroll
        for (int j = 0; j < 4; j++) {
            int c = col0 + tx * 4 + j;
            if (c < HD) g_span2[(size_t)m * HD + c] = leaky(acc[i][j] + bsm[c]);
        }
    }
}

// ---------------------------------------------------------------------------
// K10: score[b,r,x,y] = sum_q span2[beta,x,q] * v[(b,y),x,q]. Warp per elem.
// ---------------------------------------------------------------------------
__global__ __launch_bounds__(256) void k_score(float* __restrict__ out)
{
    int e = blockIdx.x * 8 + (threadIdx.x >> 5);
    int lane = threadIdx.x & 31;
    if (e >= NB * SEQ) return;
    int beta = e / SEQ;       // (b*R+r)*L + y
    int x = e % SEQ;
    int b = beta / (RANK * SEQ);
    int r = (beta / SEQ) % RANK;
    int y = beta % SEQ;
    const float* s2 = g_span2 + (size_t)e * HD;
    const float* vv = g_v + ((size_t)(b * SEQ + y) * SEQ + x) * HD;
    float s = 0.f;
    #pragma unroll
    for (int i = 0; i < 4; i++) s = fmaf(s2[lane + 32 * i], vv[lane + 32 * i], s);
    #pragma unroll
    for (int o = 16; o; o >>= 1) s += __shfl_xor_sync(0xffffffffu, s, o);
    if (lane == 0) out[((long)(b * RANK + r) * SEQ + x) * SEQ + y] = s;
}

// ---------------------------------------------------------------------------
extern "C" void kernel_launch(void* const* d_in, const int* in_sizes, int n_in,
                              void* d_out, int out_size)
{
    const float* x        = (const float*)d_in[0];
    const float* W_span   = (const float*)d_in[1];
    const float* b_span   = (const float*)d_in[2];
    const float* W_score  = (const float*)d_in[3];
    const float* b_score  = (const float*)d_in[4];
    const float* W_tri    = (const float*)d_in[5];
    const float* W_spanm  = (const float*)d_in[6];
    const float* b_spanm  = (const float*)d_in[7];
    const float* W_final  = (const float*)d_in[8];
    float* out = (float*)d_out;

    float* hidden_p;  cudaGetSymbolAddress((void**)&hidden_p,  g_hidden);
    float* scoring_p; cudaGetSymbolAddress((void**)&scoring_p, g_scoring);

    dim3 thr(256);
    // hidden [320,512] and scoring [320,256]
    k_mlp<<<dim3(8, 5), thr>>>(x, W_span,  b_span,  hidden_p,  4 * HD);
    k_mlp<<<dim3(4, 5), thr>>>(x, W_score, b_score, scoring_p, 2 * HD);
    k_hinT<<<dim3((BATCH * HD1 * SEQ + 255) / 256), thr>>>();
    k_wfT<<<dim3((HD1 * KJ + 255) / 256), thr>>>(W_final);
    k_A<<<dim3(258, 5, RANK), thr>>>(W_tri);
    k_t<<<dim3(258, 5), thr>>>();
    k_v<<<dim3(2, 3, BL), thr>>>();
    k_D<<<dim3(3, 3, NB), thr>>>();
    k_logits<<<dim3(3, 3, NB), thr>>>();
    k_softmax<<<dim3(NB * SEQ / 8), thr>>>();
    k_span<<<dim3(2, 3, NB), thr>>>();
    k_mlp2<<<dim3(2, 3200), thr>>>(W_spanm, b_spanm);
    k_score<<<dim3(NB * SEQ / 8), thr>>>(out);
}